// round 4
// baseline (speedup 1.0000x reference)
#include <cuda_runtime.h>
#include <cuda_fp16.h>

#define NGRIDS 64
#define DIMSZ  64
#define VOX    (DIMSZ*DIMSZ*DIMSZ)      // 262144
#define NPTS   (1<<19)
#define NN     64
#define DIN    128
#define NBINS  32768                    // 32^3 spatial bins

// 256 MB corner-pair buffer: voxel (g,z,y,x) holds 16B =
//   half2(ch0[x,y], ch0[x+1,y]), half2(ch0[x,y+1], ch0[x+1,y+1]),
//   half2(ch1[x,y], ch1[x+1,y]), half2(ch1[x,y+1], ch1[x+1,y+1])
__device__ uint4   g_feat[NGRIDS * VOX];
__device__ float   g_params[NGRIDS * 12];
__device__ int     g_hist[NBINS] = {0};   // zero at load; re-zeroed by scatter each call
__device__ int     g_cnt[NBINS];
__device__ float   g_xs[NPTS], g_ys[NPTS], g_zs[NPTS];
__device__ int     g_ridx[NPTS];

// ---------- packed f32x2 helpers ----------
__device__ __forceinline__ unsigned long long fma2(unsigned long long a,
                                                   unsigned long long b,
                                                   unsigned long long c) {
    unsigned long long d;
    asm("fma.rn.f32x2 %0, %1, %2, %3;" : "=l"(d) : "l"(a), "l"(b), "l"(c));
    return d;
}
__device__ __forceinline__ unsigned long long pack2(float lo, float hi) {
    unsigned long long d;
    asm("mov.b64 %0, {%1, %2};" : "=l"(d) : "f"(lo), "f"(hi));
    return d;
}
__device__ __forceinline__ void unpack2(unsigned long long v, float& lo, float& hi) {
    asm("mov.b64 {%0, %1}, %2;" : "=f"(lo), "=f"(hi) : "l"(v));
}

__device__ __forceinline__ int bin_key(float px, float py, float pz) {
    int kx = min(31, max(0, (int)((px + 1.0f) * 16.0f)));
    int ky = min(31, max(0, (int)((py + 1.0f) * 16.0f)));
    int kz = min(31, max(0, (int)((pz + 1.0f) * 16.0f)));
    return (kz << 10) | (ky << 5) | kx;
}

// ---------- launch 1: feature prep (+ histogram piggyback) ----------
__global__ void prep_feat_hist_kernel(const float* __restrict__ f,
                                      const float* __restrict__ x) {
    int i = blockIdx.x * 256 + threadIdx.x;
    if (i < NGRIDS * VOX) {
        int g   = i >> 18;
        int rem = i & (VOX - 1);
        int z = rem >> 12;
        int y = (rem >> 6) & 63;
        int xx = rem & 63;
        int xp = min(xx + 1, 63);
        int yp = min(y + 1, 63);
        const float* B0 = f + (size_t)g * 2 * VOX;
        const float* B1 = B0 + VOX;
        int r0 = (z << 12) + (y  << 6);
        int r1 = (z << 12) + (yp << 6);
        __half2 w0 = __floats2half2_rn(B0[r0 + xx], B0[r0 + xp]);
        __half2 w1 = __floats2half2_rn(B0[r1 + xx], B0[r1 + xp]);
        __half2 w2 = __floats2half2_rn(B1[r0 + xx], B1[r0 + xp]);
        __half2 w3 = __floats2half2_rn(B1[r1 + xx], B1[r1 + xp]);
        uint4 o;
        o.x = *(unsigned int*)&w0;
        o.y = *(unsigned int*)&w1;
        o.z = *(unsigned int*)&w2;
        o.w = *(unsigned int*)&w3;
        g_feat[i] = o;
    }
    // blocks 0..2047 also histogram the 2^19 points
    if (i < NPTS && blockIdx.x < (NPTS / 256)) {
        atomicAdd(&g_hist[bin_key(x[3*i], x[3*i+1], x[3*i+2])], 1);
    }
}

// ---------- launch 2: block 0 scans hist; block 1 computes affine params ----------
__global__ void scan_params_kernel(const float* __restrict__ r,
                                   const float* __restrict__ s,
                                   const float* __restrict__ t) {
    if (blockIdx.x == 1) {
        int g = threadIdx.x;
        if (g >= NGRIDS) return;
        float qw = r[4*g+0], qx = r[4*g+1], qy = r[4*g+2], qz = r[4*g+3];
        float inv = 1.0f / sqrtf(qw*qw + qx*qx + qy*qy + qz*qz);
        qw *= inv; qx *= inv; qy *= inv; qz *= inv;
        float R[9];
        R[0] = 1.f - 2.f*(qy*qy + qz*qz); R[1] = 2.f*(qx*qy - qw*qz); R[2] = 2.f*(qx*qz + qw*qy);
        R[3] = 2.f*(qx*qy + qw*qz); R[4] = 1.f - 2.f*(qx*qx + qz*qz); R[5] = 2.f*(qy*qz - qw*qx);
        R[6] = 2.f*(qx*qz - qw*qy); R[7] = 2.f*(qy*qz + qw*qx); R[8] = 1.f - 2.f*(qx*qx + qy*qy);
        #pragma unroll
        for (int i = 0; i < 3; i++) {
            float sc = 31.5f * s[3*g + i];
            g_params[g*12 + 4*i + 0] = sc * R[3*i + 0];
            g_params[g*12 + 4*i + 1] = sc * R[3*i + 1];
            g_params[g*12 + 4*i + 2] = sc * R[3*i + 2];
            g_params[g*12 + 4*i + 3] = 31.5f * (t[3*g + i] + 1.0f);
        }
        return;
    }
    __shared__ int ssum[1024];
    int tid = threadIdx.x;
    int base = tid * 32;
    int local[32];
    int acc = 0;
    #pragma unroll
    for (int i = 0; i < 32; i++) { local[i] = acc; acc += g_hist[base + i]; }
    ssum[tid] = acc;
    __syncthreads();
    for (int off = 1; off < 1024; off <<= 1) {
        int v = (tid >= off) ? ssum[tid - off] : 0;
        __syncthreads();
        ssum[tid] += v;
        __syncthreads();
    }
    int pre = (tid > 0) ? ssum[tid - 1] : 0;
    #pragma unroll
    for (int i = 0; i < 32; i++) g_cnt[base + i] = pre + local[i];
}

// ---------- launch 3: scatter (+ re-zero hist for next graph replay) ----------
__global__ void scatter_kernel(const float* __restrict__ x) {
    int n = blockIdx.x * 256 + threadIdx.x;
    if (n < NBINS) g_hist[n] = 0;     // hist already consumed by scan
    if (n >= NPTS) return;
    float px = x[3*n], py = x[3*n+1], pz = x[3*n+2];
    int pos = atomicAdd(&g_cnt[bin_key(px, py, pz)], 1);
    g_xs[pos] = px; g_ys[pos] = py; g_zs[pos] = pz;
    g_ridx[pos] = n;
}

// slot + pair-weights for a paired axis (x or y)
__device__ __forceinline__ void axis_pair(float gc, int& slot, float& wlo, float& whi) {
    float cf = floorf(gc);
    float fr = gc - cf;
    int ic = (int)cf;
    slot = min(max(ic, 0), 63);
    bool v0 = (ic >= 0) & (ic < 64);
    wlo = v0 ? (1.0f - fr) : ((ic == -1) ? fr : 0.0f);
    whi = (v0 & (ic < 63)) ? fr : 0.0f;
}

__device__ __forceinline__ void sample_grid(const uint4* __restrict__ F,
                                            float px, float py, float pz,
                                            const float* __restrict__ P,
                                            float& c0, float& c1) {
    float gx = fmaf(P[0], px, fmaf(P[1], py, fmaf(P[2],  pz, P[3])));
    float gy = fmaf(P[4], px, fmaf(P[5], py, fmaf(P[6],  pz, P[7])));
    float gz = fmaf(P[8], px, fmaf(P[9], py, fmaf(P[10], pz, P[11])));

    int sx, sy;
    float wxlo, wxhi, wylo, wyhi;
    axis_pair(gx, sx, wxlo, wxhi);
    axis_pair(gy, sy, wylo, wyhi);

    float zf = floorf(gz);
    float fz = gz - zf;
    int iz = (int)zf;
    float wz0 = (iz   >= 0 && iz   < 64) ? (1.0f - fz) : 0.0f;
    float wz1 = (iz+1 >= 0 && iz+1 < 64) ? fz          : 0.0f;
    int cz0 = min(max(iz,   0), 63);
    int cz1 = min(max(iz+1, 0), 63);

    int base = (sy << 6) + sx;
    uint4 v0 = __ldg(F + (cz0 << 12) + base);
    uint4 v1 = __ldg(F + (cz1 << 12) + base);

    {
        float2 p0 = __half22float2(*(__half2*)&v0.x);
        float2 p1 = __half22float2(*(__half2*)&v0.y);
        float2 q0 = __half22float2(*(__half2*)&v0.z);
        float2 q1 = __half22float2(*(__half2*)&v0.w);
        float r0 = fmaf(wxlo, p0.x, wxhi * p0.y);
        float r1 = fmaf(wxlo, p1.x, wxhi * p1.y);
        float s0 = fmaf(wxlo, q0.x, wxhi * q0.y);
        float s1 = fmaf(wxlo, q1.x, wxhi * q1.y);
        c0 = wz0 * fmaf(wylo, r0, wyhi * r1);
        c1 = wz0 * fmaf(wylo, s0, wyhi * s1);
    }
    {
        float2 p0 = __half22float2(*(__half2*)&v1.x);
        float2 p1 = __half22float2(*(__half2*)&v1.y);
        float2 q0 = __half22float2(*(__half2*)&v1.z);
        float2 q1 = __half22float2(*(__half2*)&v1.w);
        float r0 = fmaf(wxlo, p0.x, wxhi * p0.y);
        float r1 = fmaf(wxlo, p1.x, wxhi * p1.y);
        float s0 = fmaf(wxlo, q0.x, wxhi * q0.y);
        float s1 = fmaf(wxlo, q1.x, wxhi * q1.y);
        c0 = fmaf(wz1, fmaf(wylo, r0, wyhi * r1), c0);
        c1 = fmaf(wz1, fmaf(wylo, s0, wyhi * s1), c1);
    }
}

// ---------- launch 4: main — 2 points per thread ----------
__global__ __launch_bounds__(64, 4)
void amgsrn_main_kernel(const float* __restrict__ W0,
                        const float* __restrict__ W1,
                        const float* __restrict__ W2,
                        float* __restrict__ out) {
    extern __shared__ float smem[];
    float* sP   = smem;                  // 768
    float* sW0t = smem + 768;            // 8192  W0^T: [in=0..127][neuron=0..63]
    float* sW1  = sW0t + 8192;           // 4096
    float* sW2  = sW1 + 4096;            // 64

    int tid = threadIdx.x;
    for (int i = tid; i < NGRIDS*12; i += 64) sP[i] = g_params[i];
    for (int i = tid; i < NN*DIN; i += 64) {
        int k = i >> 7, ii = i & 127;
        sW0t[ii*64 + k] = W0[i];
    }
    for (int i = tid; i < NN*NN; i += 64) sW1[i] = W1[i];
    if (tid < NN) sW2[tid] = W2[tid];
    __syncthreads();

    int nA = blockIdx.x * 128 + tid;
    int nB = nA + 64;
    float pxA = g_xs[nA], pyA = g_ys[nA], pzA = g_zs[nA];
    float pxB = g_xs[nB], pyB = g_ys[nB], pzB = g_zs[nB];
    int origA = g_ridx[nA];
    int origB = g_ridx[nB];

    unsigned long long hA[32], hB[32];
    #pragma unroll
    for (int k = 0; k < 32; k++) { hA[k] = 0ull; hB[k] = 0ull; }

    #pragma unroll 1
    for (int g = 0; g < NGRIDS; g++) {
        const float* P = sP + g*12;
        const uint4* F = g_feat + ((size_t)g << 18);

        float c0A, c1A, c0B, c1B;
        sample_grid(F, pxA, pyA, pzA, P, c0A, c1A);
        sample_grid(F, pxB, pyB, pzB, P, c0B, c1B);

        unsigned long long a0 = pack2(c0A, c0A);
        unsigned long long a1 = pack2(c1A, c1A);
        unsigned long long b0 = pack2(c0B, c0B);
        unsigned long long b1 = pack2(c1B, c1B);
        const ulonglong2* ra = reinterpret_cast<const ulonglong2*>(sW0t + (2*g)   * 64);
        const ulonglong2* rb = reinterpret_cast<const ulonglong2*>(sW0t + (2*g+1) * 64);
        #pragma unroll
        for (int k4 = 0; k4 < 16; k4++) {
            ulonglong2 wa = ra[k4];
            ulonglong2 wb = rb[k4];
            hA[2*k4+0] = fma2(a0, wa.x, fma2(a1, wb.x, hA[2*k4+0]));
            hA[2*k4+1] = fma2(a0, wa.y, fma2(a1, wb.y, hA[2*k4+1]));
            hB[2*k4+0] = fma2(b0, wa.x, fma2(b1, wb.x, hB[2*k4+0]));
            hB[2*k4+1] = fma2(b0, wa.y, fma2(b1, wb.y, hB[2*k4+1]));
        }
    }

    // ReLU both
    #pragma unroll
    for (int k = 0; k < 32; k++) {
        float lo, hi;
        unpack2(hA[k], lo, hi);
        hA[k] = pack2(fmaxf(lo, 0.0f), fmaxf(hi, 0.0f));
        unpack2(hB[k], lo, hi);
        hB[k] = pack2(fmaxf(lo, 0.0f), fmaxf(hi, 0.0f));
    }

    float oA = 0.0f, oB = 0.0f;
    #pragma unroll 1
    for (int j = 0; j < NN; j++) {
        const ulonglong2* w = reinterpret_cast<const ulonglong2*>(sW1 + j*64);
        unsigned long long aA0 = 0ull, aA1 = 0ull, aB0 = 0ull, aB1 = 0ull;
        #pragma unroll
        for (int k4 = 0; k4 < 16; k4++) {
            ulonglong2 ww = w[k4];
            aA0 = fma2(ww.x, hA[2*k4+0], aA0);
            aA1 = fma2(ww.y, hA[2*k4+1], aA1);
            aB0 = fma2(ww.x, hB[2*k4+0], aB0);
            aB1 = fma2(ww.y, hB[2*k4+1], aB1);
        }
        float w2j = sW2[j];
        float l0, h0v, l1, h1v;
        unpack2(aA0, l0, h0v); unpack2(aA1, l1, h1v);
        oA = fmaf(w2j, fmaxf((l0 + l1) + (h0v + h1v), 0.0f), oA);
        unpack2(aB0, l0, h0v); unpack2(aB1, l1, h1v);
        oB = fmaf(w2j, fmaxf((l0 + l1) + (h0v + h1v), 0.0f), oB);
    }
    out[origA] = oA;
    out[origB] = oB;
}

extern "C" void kernel_launch(void* const* d_in, const int* in_sizes, int n_in,
                              void* d_out, int out_size) {
    const float* x  = (const float*)d_in[0];
    const float* r  = (const float*)d_in[1];
    const float* s  = (const float*)d_in[2];
    const float* t  = (const float*)d_in[3];
    const float* f  = (const float*)d_in[4];
    const float* W0 = (const float*)d_in[5];
    const float* W1 = (const float*)d_in[6];
    const float* W2 = (const float*)d_in[7];
    float* out = (float*)d_out;

    const int SMEM_BYTES = (768 + 8192 + 4096 + 64) * 4;  // 52480
    cudaFuncSetAttribute(amgsrn_main_kernel,
                         cudaFuncAttributeMaxDynamicSharedMemorySize, SMEM_BYTES);

    prep_feat_hist_kernel<<<(NGRIDS * VOX + 255) / 256, 256>>>(f, x);  // 1
    scan_params_kernel<<<2, 1024>>>(r, s, t);                          // 2
    scatter_kernel<<<(NPTS + 255) / 256, 256>>>(x);                    // 3
    amgsrn_main_kernel<<<NPTS / 128, 64, SMEM_BYTES>>>(W0, W1, W2, out);  // 4 (ncu slot)
}

// round 6
// speedup vs baseline: 1.6506x; 1.6506x over previous
#include <cuda_runtime.h>
#include <cuda_fp16.h>
#include <cstdint>

#define NGRIDS 64
#define DIMSZ  64
#define VOX    (DIMSZ*DIMSZ*DIMSZ)      // 262144
#define NPTS   (1<<19)
#define NN     64
#define NBINS  32768

// 256 MB corner-pair buffer (16B per voxel)
__device__ uint4   g_feat[NGRIDS * VOX];
__device__ float   g_params[NGRIDS * 12];
__device__ int     g_hist[NBINS] = {0};
__device__ int     g_cnt[NBINS];
__device__ float   g_xs[NPTS], g_ys[NPTS], g_zs[NPTS];
__device__ int     g_ridx[NPTS];

// ---------------- smem layout for fused kernel (bytes) ----------------
#define STRA   136                       // halfs per A row (272B, 16B-aligned)
#define STRB0  136                       // halfs per W0 row
#define STRB1  72                        // halfs per W1 row (144B)
#define A_OFF   0
#define B0_OFF  (256 * STRA * 2)                 // 69632
#define B1_OFF  (B0_OFF + 64 * STRB0 * 2)        // 87040
#define P_OFF   (B1_OFF + 64 * STRB1 * 2)        // 96256
#define W2_OFF  (P_OFF + NGRIDS * 12 * 4)        // 99328
#define SMEM_TOTAL (W2_OFF + 64 * 4)             // 99584

// ---------------- helpers ----------------
__device__ __forceinline__ uint32_t smem_u32(const void* p) {
    return (uint32_t)__cvta_generic_to_shared(p);
}
__device__ __forceinline__ void ldsm4(uint32_t* r, uint32_t addr) {
    asm volatile("ldmatrix.sync.aligned.m8n8.x4.shared.b16 {%0,%1,%2,%3}, [%4];"
        : "=r"(r[0]), "=r"(r[1]), "=r"(r[2]), "=r"(r[3]) : "r"(addr));
}
__device__ __forceinline__ void mma16816(float* c, const uint32_t* a,
                                         uint32_t b0, uint32_t b1) {
    asm volatile("mma.sync.aligned.m16n8k16.row.col.f32.f16.f16.f32 "
        "{%0,%1,%2,%3}, {%4,%5,%6,%7}, {%8,%9}, {%0,%1,%2,%3};"
        : "+f"(c[0]), "+f"(c[1]), "+f"(c[2]), "+f"(c[3])
        : "r"(a[0]), "r"(a[1]), "r"(a[2]), "r"(a[3]), "r"(b0), "r"(b1));
}
__device__ __forceinline__ uint32_t rpack(float a, float b) {
    __half2 h = __floats2half2_rn(fmaxf(a, 0.0f), fmaxf(b, 0.0f));
    return *(uint32_t*)&h;
}
__device__ __forceinline__ int bin_key(float px, float py, float pz) {
    int kx = min(31, max(0, (int)((px + 1.0f) * 16.0f)));
    int ky = min(31, max(0, (int)((py + 1.0f) * 16.0f)));
    int kz = min(31, max(0, (int)((pz + 1.0f) * 16.0f)));
    return (kz << 10) | (ky << 5) | kx;
}
__device__ __forceinline__ void axis_pair(float gc, int& slot, float& wlo, float& whi) {
    float cf = floorf(gc);
    float fr = gc - cf;
    int ic = (int)cf;
    slot = min(max(ic, 0), 63);
    bool v0 = (ic >= 0) & (ic < 64);
    wlo = v0 ? (1.0f - fr) : ((ic == -1) ? fr : 0.0f);
    whi = (v0 & (ic < 63)) ? fr : 0.0f;
}
__device__ __forceinline__ void sample_grid(const uint4* __restrict__ F,
                                            float px, float py, float pz,
                                            const float* __restrict__ P,
                                            float& c0, float& c1) {
    float gx = fmaf(P[0], px, fmaf(P[1], py, fmaf(P[2],  pz, P[3])));
    float gy = fmaf(P[4], px, fmaf(P[5], py, fmaf(P[6],  pz, P[7])));
    float gz = fmaf(P[8], px, fmaf(P[9], py, fmaf(P[10], pz, P[11])));

    int sx, sy;
    float wxlo, wxhi, wylo, wyhi;
    axis_pair(gx, sx, wxlo, wxhi);
    axis_pair(gy, sy, wylo, wyhi);

    float zf = floorf(gz);
    float fz = gz - zf;
    int iz = (int)zf;
    float wz0 = (iz   >= 0 && iz   < 64) ? (1.0f - fz) : 0.0f;
    float wz1 = (iz+1 >= 0 && iz+1 < 64) ? fz          : 0.0f;
    int cz0 = min(max(iz,   0), 63);
    int cz1 = min(max(iz+1, 0), 63);

    int base = (sy << 6) + sx;
    uint4 v0 = __ldg(F + (cz0 << 12) + base);
    uint4 v1 = __ldg(F + (cz1 << 12) + base);
    {
        float2 p0 = __half22float2(*(__half2*)&v0.x);
        float2 p1 = __half22float2(*(__half2*)&v0.y);
        float2 q0 = __half22float2(*(__half2*)&v0.z);
        float2 q1 = __half22float2(*(__half2*)&v0.w);
        float r0 = fmaf(wxlo, p0.x, wxhi * p0.y);
        float r1 = fmaf(wxlo, p1.x, wxhi * p1.y);
        float s0 = fmaf(wxlo, q0.x, wxhi * q0.y);
        float s1 = fmaf(wxlo, q1.x, wxhi * q1.y);
        c0 = wz0 * fmaf(wylo, r0, wyhi * r1);
        c1 = wz0 * fmaf(wylo, s0, wyhi * s1);
    }
    {
        float2 p0 = __half22float2(*(__half2*)&v1.x);
        float2 p1 = __half22float2(*(__half2*)&v1.y);
        float2 q0 = __half22float2(*(__half2*)&v1.z);
        float2 q1 = __half22float2(*(__half2*)&v1.w);
        float r0 = fmaf(wxlo, p0.x, wxhi * p0.y);
        float r1 = fmaf(wxlo, p1.x, wxhi * p1.y);
        float s0 = fmaf(wxlo, q0.x, wxhi * q0.y);
        float s1 = fmaf(wxlo, q1.x, wxhi * q1.y);
        c0 = fmaf(wz1, fmaf(wylo, r0, wyhi * r1), c0);
        c1 = fmaf(wz1, fmaf(wylo, s0, wyhi * s1), c1);
    }
}

// ================== launch 1: feature prep + histogram ==================
__global__ void prep_feat_hist_kernel(const float* __restrict__ f,
                                      const float* __restrict__ x) {
    int i = blockIdx.x * 256 + threadIdx.x;
    if (i < NGRIDS * VOX) {
        int g   = i >> 18;
        int rem = i & (VOX - 1);
        int z = rem >> 12;
        int y = (rem >> 6) & 63;
        int xx = rem & 63;
        int xp = min(xx + 1, 63);
        int yp = min(y + 1, 63);
        const float* B0 = f + (size_t)g * 2 * VOX;
        const float* B1 = B0 + VOX;
        int r0 = (z << 12) + (y  << 6);
        int r1 = (z << 12) + (yp << 6);
        __half2 w0 = __floats2half2_rn(B0[r0 + xx], B0[r0 + xp]);
        __half2 w1 = __floats2half2_rn(B0[r1 + xx], B0[r1 + xp]);
        __half2 w2 = __floats2half2_rn(B1[r0 + xx], B1[r0 + xp]);
        __half2 w3 = __floats2half2_rn(B1[r1 + xx], B1[r1 + xp]);
        uint4 o;
        o.x = *(unsigned int*)&w0;
        o.y = *(unsigned int*)&w1;
        o.z = *(unsigned int*)&w2;
        o.w = *(unsigned int*)&w3;
        g_feat[i] = o;
    }
    if (i < NPTS && blockIdx.x < (NPTS / 256)) {
        atomicAdd(&g_hist[bin_key(x[3*i], x[3*i+1], x[3*i+2])], 1);
    }
}

// ================== launch 2: scan + params ==================
__global__ void scan_params_kernel(const float* __restrict__ r,
                                   const float* __restrict__ s,
                                   const float* __restrict__ t) {
    if (blockIdx.x == 1) {
        int g = threadIdx.x;
        if (g >= NGRIDS) return;
        float qw = r[4*g+0], qx = r[4*g+1], qy = r[4*g+2], qz = r[4*g+3];
        float inv = 1.0f / sqrtf(qw*qw + qx*qx + qy*qy + qz*qz);
        qw *= inv; qx *= inv; qy *= inv; qz *= inv;
        float R[9];
        R[0] = 1.f - 2.f*(qy*qy + qz*qz); R[1] = 2.f*(qx*qy - qw*qz); R[2] = 2.f*(qx*qz + qw*qy);
        R[3] = 2.f*(qx*qy + qw*qz); R[4] = 1.f - 2.f*(qx*qx + qz*qz); R[5] = 2.f*(qy*qz - qw*qx);
        R[6] = 2.f*(qx*qz - qw*qy); R[7] = 2.f*(qy*qz + qw*qx); R[8] = 1.f - 2.f*(qx*qx + qy*qy);
        #pragma unroll
        for (int i = 0; i < 3; i++) {
            float sc = 31.5f * s[3*g + i];
            g_params[g*12 + 4*i + 0] = sc * R[3*i + 0];
            g_params[g*12 + 4*i + 1] = sc * R[3*i + 1];
            g_params[g*12 + 4*i + 2] = sc * R[3*i + 2];
            g_params[g*12 + 4*i + 3] = 31.5f * (t[3*g + i] + 1.0f);
        }
        return;
    }
    __shared__ int ssum[1024];
    int tid = threadIdx.x;
    int base = tid * 32;
    int local[32];
    int acc = 0;
    #pragma unroll
    for (int i = 0; i < 32; i++) { local[i] = acc; acc += g_hist[base + i]; }
    ssum[tid] = acc;
    __syncthreads();
    for (int off = 1; off < 1024; off <<= 1) {
        int v = (tid >= off) ? ssum[tid - off] : 0;
        __syncthreads();
        ssum[tid] += v;
        __syncthreads();
    }
    int pre = (tid > 0) ? ssum[tid - 1] : 0;
    #pragma unroll
    for (int i = 0; i < 32; i++) g_cnt[base + i] = pre + local[i];
}

// ================== launch 3: scatter (+ hist re-zero) ==================
__global__ void scatter_kernel(const float* __restrict__ x) {
    int n = blockIdx.x * 256 + threadIdx.x;
    if (n < NBINS) g_hist[n] = 0;
    if (n >= NPTS) return;
    float px = x[3*n], py = x[3*n+1], pz = x[3*n+2];
    int pos = atomicAdd(&g_cnt[bin_key(px, py, pz)], 1);
    g_xs[pos] = px; g_ys[pos] = py; g_zs[pos] = pz;
    g_ridx[pos] = n;
}

// ================== launch 4: fused gather + HMMA MLP ==================
__global__ __launch_bounds__(256, 2)
void amgsrn_fused_kernel(const float* __restrict__ W0,
                         const float* __restrict__ W1,
                         const float* __restrict__ W2,
                         float* __restrict__ out) {
    extern __shared__ char smem_raw[];
    __half* sA  = (__half*)(smem_raw + A_OFF);    // [256][STRA]
    __half* sB0 = (__half*)(smem_raw + B0_OFF);   // [64][STRB0]  W0 fp16
    __half* sB1 = (__half*)(smem_raw + B1_OFF);   // [64][STRB1]  W1 fp16
    float*  sP  = (float*)(smem_raw + P_OFF);
    float*  sW2 = (float*)(smem_raw + W2_OFF);

    int tid = threadIdx.x;

    // ---- prologue: weights/params -> smem ----
    for (int i = tid; i < 64 * 128; i += 256) {
        int n = i >> 7, k = i & 127;
        sB0[n * STRB0 + k] = __float2half_rn(W0[i]);
    }
    for (int i = tid; i < 64 * 64; i += 256) {
        int n = i >> 6, k = i & 63;
        sB1[n * STRB1 + k] = __float2half_rn(W1[i]);
    }
    for (int i = tid; i < NGRIDS * 12; i += 256) sP[i] = g_params[i];
    if (tid < NN) sW2[tid] = W2[tid];
    __syncthreads();

    // ---- phase 1: gather 64 grids -> sA[tid][2g..2g+1] fp16 ----
    {
        int p = blockIdx.x * 256 + tid;
        float px = g_xs[p], py = g_ys[p], pz = g_zs[p];
        uint32_t* aRow = (uint32_t*)(sA + tid * STRA);
        #pragma unroll 2
        for (int g = 0; g < NGRIDS; g++) {
            float c0, c1;
            sample_grid(g_feat + ((size_t)g << 18), px, py, pz, sP + g * 12, c0, c1);
            __half2 hp = __floats2half2_rn(c0, c1);
            aRow[g] = *(uint32_t*)&hp;
        }
    }
    __syncthreads();

    // ---- phase 2: per-warp MLP over its 32 points ----
    int w = tid >> 5, L = tid & 31;
    int lm = L >> 3;       // ldmatrix matrix index
    int lr = L & 7;

    // A (layer0): row = 32w + m*16 + (lm&1)*8 + lr ; col = 16s + (lm>>1)*8
    uint32_t aAddr = smem_u32(sA) + ((uint32_t)(w * 32 + (lm & 1) * 8 + lr) * STRA
                                     + (uint32_t)(lm >> 1) * 8) * 2;
    // B: row = j*8 + ((L>>4)&1)*8 + lr ; col = k0 + ((L>>3)&1)*8
    uint32_t b0Addr = smem_u32(sB0) + ((uint32_t)(((L >> 4) & 1) * 8 + lr) * STRB0
                                       + (uint32_t)((L >> 3) & 1) * 8) * 2;
    uint32_t b1Addr = smem_u32(sB1) + ((uint32_t)(((L >> 4) & 1) * 8 + lr) * STRB1
                                       + (uint32_t)((L >> 3) & 1) * 8) * 2;

    float C0[2][8][4];
    #pragma unroll
    for (int m = 0; m < 2; m++)
        #pragma unroll
        for (int nt = 0; nt < 8; nt++)
            #pragma unroll
            for (int q = 0; q < 4; q++) C0[m][nt][q] = 0.0f;

    // layer0: [32 x 128] @ W0^T[128 x 64]
    #pragma unroll
    for (int s = 0; s < 8; s++) {
        uint32_t a0[4], a1[4];
        ldsm4(a0, aAddr + (uint32_t)(16 * s) * 2);
        ldsm4(a1, aAddr + (uint32_t)(16 * STRA + 16 * s) * 2);
        #pragma unroll
        for (int jp = 0; jp < 4; jp++) {
            uint32_t b[4];
            ldsm4(b, b0Addr + (uint32_t)(jp * 16 * STRB0 + 16 * s) * 2);
            mma16816(C0[0][2*jp+0], a0, b[0], b[1]);
            mma16816(C0[0][2*jp+1], a0, b[2], b[3]);
            mma16816(C0[1][2*jp+0], a1, b[0], b[1]);
            mma16816(C0[1][2*jp+1], a1, b[2], b[3]);
        }
    }

    // relu + pack: D fragment -> A fragment for layer1 (in registers)
    uint32_t A1[2][4][4];
    #pragma unroll
    for (int m = 0; m < 2; m++)
        #pragma unroll
        for (int s = 0; s < 4; s++) {
            A1[m][s][0] = rpack(C0[m][2*s+0][0], C0[m][2*s+0][1]);
            A1[m][s][1] = rpack(C0[m][2*s+0][2], C0[m][2*s+0][3]);
            A1[m][s][2] = rpack(C0[m][2*s+1][0], C0[m][2*s+1][1]);
            A1[m][s][3] = rpack(C0[m][2*s+1][2], C0[m][2*s+1][3]);
        }

    float C1[2][8][4];
    #pragma unroll
    for (int m = 0; m < 2; m++)
        #pragma unroll
        for (int nt = 0; nt < 8; nt++)
            #pragma unroll
            for (int q = 0; q < 4; q++) C1[m][nt][q] = 0.0f;

    // layer1: [32 x 64] @ W1^T[64 x 64]
    #pragma unroll
    for (int s = 0; s < 4; s++) {
        #pragma unroll
        for (int jp = 0; jp < 4; jp++) {
            uint32_t b[4];
            ldsm4(b, b1Addr + (uint32_t)(jp * 16 * STRB1 + 16 * s) * 2);
            mma16816(C1[0][2*jp+0], A1[0][s], b[0], b[1]);
            mma16816(C1[0][2*jp+1], A1[0][s], b[2], b[3]);
            mma16816(C1[1][2*jp+0], A1[1][s], b[0], b[1]);
            mma16816(C1[1][2*jp+1], A1[1][s], b[2], b[3]);
        }
    }

    // epilogue: out = relu(h1) . W2, reduce over lanes within group-of-4
    int tq = L & 3, gq = L >> 2;
    float2 w2v[8];
    #pragma unroll
    for (int nt = 0; nt < 8; nt++) {
        w2v[nt].x = sW2[nt * 8 + 2 * tq + 0];
        w2v[nt].y = sW2[nt * 8 + 2 * tq + 1];
    }
    int base = blockIdx.x * 256 + w * 32;
    #pragma unroll
    for (int m = 0; m < 2; m++) {
        float p01 = 0.0f, p23 = 0.0f;
        #pragma unroll
        for (int nt = 0; nt < 8; nt++) {
            p01 = fmaf(fmaxf(C1[m][nt][0], 0.0f), w2v[nt].x, p01);
            p01 = fmaf(fmaxf(C1[m][nt][1], 0.0f), w2v[nt].y, p01);
            p23 = fmaf(fmaxf(C1[m][nt][2], 0.0f), w2v[nt].x, p23);
            p23 = fmaf(fmaxf(C1[m][nt][3], 0.0f), w2v[nt].y, p23);
        }
        p01 += __shfl_xor_sync(0xffffffffu, p01, 1);
        p01 += __shfl_xor_sync(0xffffffffu, p01, 2);
        p23 += __shfl_xor_sync(0xffffffffu, p23, 1);
        p23 += __shfl_xor_sync(0xffffffffu, p23, 2);
        if (tq == 0) {
            out[g_ridx[base + m * 16 + gq]]     = p01;
            out[g_ridx[base + m * 16 + 8 + gq]] = p23;
        }
    }
}

extern "C" void kernel_launch(void* const* d_in, const int* in_sizes, int n_in,
                              void* d_out, int out_size) {
    const float* x  = (const float*)d_in[0];
    const float* r  = (const float*)d_in[1];
    const float* s  = (const float*)d_in[2];
    const float* t  = (const float*)d_in[3];
    const float* f  = (const float*)d_in[4];
    const float* W0 = (const float*)d_in[5];
    const float* W1 = (const float*)d_in[6];
    const float* W2 = (const float*)d_in[7];
    float* out = (float*)d_out;

    cudaFuncSetAttribute(amgsrn_fused_kernel,
                         cudaFuncAttributeMaxDynamicSharedMemorySize, SMEM_TOTAL);

    prep_feat_hist_kernel<<<(NGRIDS * VOX + 255) / 256, 256>>>(f, x);   // 1
    scan_params_kernel<<<2, 1024>>>(r, s, t);                           // 2
    scatter_kernel<<<(NPTS + 255) / 256, 256>>>(x);                     // 3
    amgsrn_fused_kernel<<<NPTS / 256, 256, SMEM_TOTAL>>>(W0, W1, W2, out);  // 4 (ncu slot)
}

// round 7
// speedup vs baseline: 1.7357x; 1.0516x over previous
#include <cuda_runtime.h>
#include <cuda_fp16.h>
#include <cstdint>

#define NGRIDS 64
#define DIMSZ  64
#define VOX    (DIMSZ*DIMSZ*DIMSZ)      // 262144
#define NPTS   (1<<19)
#define NN     64
#define NBINS  32768

// 256 MB corner-pair buffer (16B per voxel)
__device__ uint4   g_feat[NGRIDS * VOX];
__device__ float   g_params[NGRIDS * 12];
__device__ int     g_hist[NBINS] = {0};
__device__ int     g_cnt[NBINS];
__device__ float   g_xs[NPTS], g_ys[NPTS], g_zs[NPTS];
__device__ int     g_ridx[NPTS];

// ---------------- smem layout for fused kernel (bytes) ----------------
#define STRA   136                       // halfs per A row (272B, 16B-aligned)
#define STRB0  136
#define STRB1  72
#define A_OFF   0
#define B0_OFF  (256 * STRA * 2)                 // 69632
#define B1_OFF  (B0_OFF + 64 * STRB0 * 2)        // 87040
#define P_OFF   (B1_OFF + 64 * STRB1 * 2)        // 96256
#define W2_OFF  (P_OFF + NGRIDS * 12 * 4)        // 99328
#define SMEM_TOTAL (W2_OFF + 64 * 4)             // 99584

// ---------------- helpers ----------------
__device__ __forceinline__ uint32_t smem_u32(const void* p) {
    return (uint32_t)__cvta_generic_to_shared(p);
}
__device__ __forceinline__ void ldsm4(uint32_t* r, uint32_t addr) {
    asm volatile("ldmatrix.sync.aligned.m8n8.x4.shared.b16 {%0,%1,%2,%3}, [%4];"
        : "=r"(r[0]), "=r"(r[1]), "=r"(r[2]), "=r"(r[3]) : "r"(addr));
}
__device__ __forceinline__ void mma16816(float* c, const uint32_t* a,
                                         uint32_t b0, uint32_t b1) {
    asm volatile("mma.sync.aligned.m16n8k16.row.col.f32.f16.f16.f32 "
        "{%0,%1,%2,%3}, {%4,%5,%6,%7}, {%8,%9}, {%0,%1,%2,%3};"
        : "+f"(c[0]), "+f"(c[1]), "+f"(c[2]), "+f"(c[3])
        : "r"(a[0]), "r"(a[1]), "r"(a[2]), "r"(a[3]), "r"(b0), "r"(b1));
}
__device__ __forceinline__ uint32_t rpack(float a, float b) {
    __half2 h = __floats2half2_rn(fmaxf(a, 0.0f), fmaxf(b, 0.0f));
    return *(uint32_t*)&h;
}
__device__ __forceinline__ int bin_key(float px, float py, float pz) {
    int kx = min(31, max(0, (int)((px + 1.0f) * 16.0f)));
    int ky = min(31, max(0, (int)((py + 1.0f) * 16.0f)));
    int kz = min(31, max(0, (int)((pz + 1.0f) * 16.0f)));
    return (kz << 10) | (ky << 5) | kx;
}
__device__ __forceinline__ void axis_pair(float gc, int& slot, float& wlo, float& whi) {
    float cf = floorf(gc);
    float fr = gc - cf;
    int ic = (int)cf;
    slot = min(max(ic, 0), 63);
    bool v0 = (ic >= 0) & (ic < 64);
    wlo = v0 ? (1.0f - fr) : ((ic == -1) ? fr : 0.0f);
    whi = (v0 & (ic < 63)) ? fr : 0.0f;
}
// combine one grid's two slab fetches into (c0, c1)
__device__ __forceinline__ float2 tri_combine(uint4 v0, uint4 v1,
                                              float wxlo, float wxhi,
                                              float wylo, float wyhi,
                                              float wz0,  float wz1) {
    float c0, c1;
    {
        float2 p0 = __half22float2(*(__half2*)&v0.x);
        float2 p1 = __half22float2(*(__half2*)&v0.y);
        float2 q0 = __half22float2(*(__half2*)&v0.z);
        float2 q1 = __half22float2(*(__half2*)&v0.w);
        float r0 = fmaf(wxlo, p0.x, wxhi * p0.y);
        float r1 = fmaf(wxlo, p1.x, wxhi * p1.y);
        float s0 = fmaf(wxlo, q0.x, wxhi * q0.y);
        float s1 = fmaf(wxlo, q1.x, wxhi * q1.y);
        c0 = wz0 * fmaf(wylo, r0, wyhi * r1);
        c1 = wz0 * fmaf(wylo, s0, wyhi * s1);
    }
    {
        float2 p0 = __half22float2(*(__half2*)&v1.x);
        float2 p1 = __half22float2(*(__half2*)&v1.y);
        float2 q0 = __half22float2(*(__half2*)&v1.z);
        float2 q1 = __half22float2(*(__half2*)&v1.w);
        float r0 = fmaf(wxlo, p0.x, wxhi * p0.y);
        float r1 = fmaf(wxlo, p1.x, wxhi * p1.y);
        float s0 = fmaf(wxlo, q0.x, wxhi * q0.y);
        float s1 = fmaf(wxlo, q1.x, wxhi * q1.y);
        c0 = fmaf(wz1, fmaf(wylo, r0, wyhi * r1), c0);
        c1 = fmaf(wz1, fmaf(wylo, s0, wyhi * s1), c1);
    }
    return make_float2(c0, c1);
}

// ================== launch 1: feature prep + histogram ==================
__global__ void prep_feat_hist_kernel(const float* __restrict__ f,
                                      const float* __restrict__ x) {
    int i = blockIdx.x * 256 + threadIdx.x;
    if (i < NGRIDS * VOX) {
        int g   = i >> 18;
        int rem = i & (VOX - 1);
        int z = rem >> 12;
        int y = (rem >> 6) & 63;
        int xx = rem & 63;
        int xp = min(xx + 1, 63);
        int yp = min(y + 1, 63);
        const float* B0 = f + (size_t)g * 2 * VOX;
        const float* B1 = B0 + VOX;
        int r0 = (z << 12) + (y  << 6);
        int r1 = (z << 12) + (yp << 6);
        __half2 w0 = __floats2half2_rn(B0[r0 + xx], B0[r0 + xp]);
        __half2 w1 = __floats2half2_rn(B0[r1 + xx], B0[r1 + xp]);
        __half2 w2 = __floats2half2_rn(B1[r0 + xx], B1[r0 + xp]);
        __half2 w3 = __floats2half2_rn(B1[r1 + xx], B1[r1 + xp]);
        uint4 o;
        o.x = *(unsigned int*)&w0;
        o.y = *(unsigned int*)&w1;
        o.z = *(unsigned int*)&w2;
        o.w = *(unsigned int*)&w3;
        g_feat[i] = o;
    }
    if (i < NPTS && blockIdx.x < (NPTS / 256)) {
        atomicAdd(&g_hist[bin_key(x[3*i], x[3*i+1], x[3*i+2])], 1);
    }
}

// ================== launch 2: scan + params ==================
__global__ void scan_params_kernel(const float* __restrict__ r,
                                   const float* __restrict__ s,
                                   const float* __restrict__ t) {
    if (blockIdx.x == 1) {
        int g = threadIdx.x;
        if (g >= NGRIDS) return;
        float qw = r[4*g+0], qx = r[4*g+1], qy = r[4*g+2], qz = r[4*g+3];
        float inv = 1.0f / sqrtf(qw*qw + qx*qx + qy*qy + qz*qz);
        qw *= inv; qx *= inv; qy *= inv; qz *= inv;
        float R[9];
        R[0] = 1.f - 2.f*(qy*qy + qz*qz); R[1] = 2.f*(qx*qy - qw*qz); R[2] = 2.f*(qx*qz + qw*qy);
        R[3] = 2.f*(qx*qy + qw*qz); R[4] = 1.f - 2.f*(qx*qx + qz*qz); R[5] = 2.f*(qy*qz - qw*qx);
        R[6] = 2.f*(qx*qz - qw*qy); R[7] = 2.f*(qy*qz + qw*qx); R[8] = 1.f - 2.f*(qx*qx + qy*qy);
        #pragma unroll
        for (int i = 0; i < 3; i++) {
            float sc = 31.5f * s[3*g + i];
            g_params[g*12 + 4*i + 0] = sc * R[3*i + 0];
            g_params[g*12 + 4*i + 1] = sc * R[3*i + 1];
            g_params[g*12 + 4*i + 2] = sc * R[3*i + 2];
            g_params[g*12 + 4*i + 3] = 31.5f * (t[3*g + i] + 1.0f);
        }
        return;
    }
    __shared__ int ssum[1024];
    int tid = threadIdx.x;
    int base = tid * 32;
    int local[32];
    int acc = 0;
    #pragma unroll
    for (int i = 0; i < 32; i++) { local[i] = acc; acc += g_hist[base + i]; }
    ssum[tid] = acc;
    __syncthreads();
    for (int off = 1; off < 1024; off <<= 1) {
        int v = (tid >= off) ? ssum[tid - off] : 0;
        __syncthreads();
        ssum[tid] += v;
        __syncthreads();
    }
    int pre = (tid > 0) ? ssum[tid - 1] : 0;
    #pragma unroll
    for (int i = 0; i < 32; i++) g_cnt[base + i] = pre + local[i];
}

// ================== launch 3: scatter (+ hist re-zero) ==================
__global__ void scatter_kernel(const float* __restrict__ x) {
    int n = blockIdx.x * 256 + threadIdx.x;
    if (n < NBINS) g_hist[n] = 0;
    if (n >= NPTS) return;
    float px = x[3*n], py = x[3*n+1], pz = x[3*n+2];
    int pos = atomicAdd(&g_cnt[bin_key(px, py, pz)], 1);
    g_xs[pos] = px; g_ys[pos] = py; g_zs[pos] = pz;
    g_ridx[pos] = n;
}

// ================== launch 4: fused gather + HMMA MLP ==================
__global__ __launch_bounds__(256, 2)
void amgsrn_fused_kernel(const float* __restrict__ W0,
                         const float* __restrict__ W1,
                         const float* __restrict__ W2,
                         float* __restrict__ out) {
    extern __shared__ char smem_raw[];
    __half* sA  = (__half*)(smem_raw + A_OFF);    // [256][STRA]
    __half* sB0 = (__half*)(smem_raw + B0_OFF);   // [64][STRB0]  W0 fp16
    __half* sB1 = (__half*)(smem_raw + B1_OFF);   // [64][STRB1]  W1 fp16
    float*  sP  = (float*)(smem_raw + P_OFF);
    float*  sW2 = (float*)(smem_raw + W2_OFF);

    int tid = threadIdx.x;

    // ---- prologue: weights/params -> smem ----
    for (int i = tid; i < 64 * 128; i += 256) {
        int n = i >> 7, k = i & 127;
        sB0[n * STRB0 + k] = __float2half_rn(W0[i]);
    }
    for (int i = tid; i < 64 * 64; i += 256) {
        int n = i >> 6, k = i & 63;
        sB1[n * STRB1 + k] = __float2half_rn(W1[i]);
    }
    for (int i = tid; i < NGRIDS * 12; i += 256) sP[i] = g_params[i];
    if (tid < NN) sW2[tid] = W2[tid];
    __syncthreads();

    // ---- phase 1: gather 64 grids, 4 at a time (8 loads in flight) ----
    {
        int p = blockIdx.x * 256 + tid;
        float px = g_xs[p], py = g_ys[p], pz = g_zs[p];
        uint32_t* aRow = (uint32_t*)(sA + tid * STRA);
        #pragma unroll 1
        for (int c = 0; c < 16; c++) {
            uint4 v0[4], v1[4];
            float wxlo[4], wxhi[4], wylo[4], wyhi[4], wz0a[4], wz1a[4];
            #pragma unroll
            for (int j = 0; j < 4; j++) {
                int g = c * 4 + j;
                const float* P = sP + g * 12;
                float gx = fmaf(P[0], px, fmaf(P[1], py, fmaf(P[2],  pz, P[3])));
                float gy = fmaf(P[4], px, fmaf(P[5], py, fmaf(P[6],  pz, P[7])));
                float gz = fmaf(P[8], px, fmaf(P[9], py, fmaf(P[10], pz, P[11])));
                int sx, sy;
                axis_pair(gx, sx, wxlo[j], wxhi[j]);
                axis_pair(gy, sy, wylo[j], wyhi[j]);
                float zf = floorf(gz);
                float fz = gz - zf;
                int iz = (int)zf;
                wz0a[j] = (iz   >= 0 && iz   < 64) ? (1.0f - fz) : 0.0f;
                wz1a[j] = (iz+1 >= 0 && iz+1 < 64) ? fz          : 0.0f;
                int cz0 = min(max(iz,   0), 63);
                int cz1 = min(max(iz+1, 0), 63);
                const uint4* F = g_feat + ((size_t)g << 18);
                int base = (sy << 6) + sx;
                v0[j] = __ldg(F + (cz0 << 12) + base);
                v1[j] = __ldg(F + (cz1 << 12) + base);
            }
            uint32_t fr[4];
            #pragma unroll
            for (int j = 0; j < 4; j++) {
                float2 cc = tri_combine(v0[j], v1[j], wxlo[j], wxhi[j],
                                        wylo[j], wyhi[j], wz0a[j], wz1a[j]);
                __half2 hp = __floats2half2_rn(cc.x, cc.y);
                fr[j] = *(uint32_t*)&hp;
            }
            *(uint4*)(aRow + c * 4) = make_uint4(fr[0], fr[1], fr[2], fr[3]);
        }
    }
    __syncthreads();

    // ---- phase 2: per-warp MLP over its 32 points ----
    int w = tid >> 5, L = tid & 31;
    int lm = L >> 3;
    int lr = L & 7;

    uint32_t aAddr = smem_u32(sA) + ((uint32_t)(w * 32 + (lm & 1) * 8 + lr) * STRA
                                     + (uint32_t)(lm >> 1) * 8) * 2;
    uint32_t b0Addr = smem_u32(sB0) + ((uint32_t)(((L >> 4) & 1) * 8 + lr) * STRB0
                                       + (uint32_t)((L >> 3) & 1) * 8) * 2;
    uint32_t b1Addr = smem_u32(sB1) + ((uint32_t)(((L >> 4) & 1) * 8 + lr) * STRB1
                                       + (uint32_t)((L >> 3) & 1) * 8) * 2;

    float C0[2][8][4];
    #pragma unroll
    for (int m = 0; m < 2; m++)
        #pragma unroll
        for (int nt = 0; nt < 8; nt++)
            #pragma unroll
            for (int q = 0; q < 4; q++) C0[m][nt][q] = 0.0f;

    #pragma unroll
    for (int s = 0; s < 8; s++) {
        uint32_t a0[4], a1[4];
        ldsm4(a0, aAddr + (uint32_t)(16 * s) * 2);
        ldsm4(a1, aAddr + (uint32_t)(16 * STRA + 16 * s) * 2);
        #pragma unroll
        for (int jp = 0; jp < 4; jp++) {
            uint32_t b[4];
            ldsm4(b, b0Addr + (uint32_t)(jp * 16 * STRB0 + 16 * s) * 2);
            mma16816(C0[0][2*jp+0], a0, b[0], b[1]);
            mma16816(C0[0][2*jp+1], a0, b[2], b[3]);
            mma16816(C0[1][2*jp+0], a1, b[0], b[1]);
            mma16816(C0[1][2*jp+1], a1, b[2], b[3]);
        }
    }

    uint32_t A1[2][4][4];
    #pragma unroll
    for (int m = 0; m < 2; m++)
        #pragma unroll
        for (int s = 0; s < 4; s++) {
            A1[m][s][0] = rpack(C0[m][2*s+0][0], C0[m][2*s+0][1]);
            A1[m][s][1] = rpack(C0[m][2*s+0][2], C0[m][2*s+0][3]);
            A1[m][s][2] = rpack(C0[m][2*s+1][0], C0[m][2*s+1][1]);
            A1[m][s][3] = rpack(C0[m][2*s+1][2], C0[m][2*s+1][3]);
        }

    float C1[2][8][4];
    #pragma unroll
    for (int m = 0; m < 2; m++)
        #pragma unroll
        for (int nt = 0; nt < 8; nt++)
            #pragma unroll
            for (int q = 0; q < 4; q++) C1[m][nt][q] = 0.0f;

    #pragma unroll
    for (int s = 0; s < 4; s++) {
        #pragma unroll
        for (int jp = 0; jp < 4; jp++) {
            uint32_t b[4];
            ldsm4(b, b1Addr + (uint32_t)(jp * 16 * STRB1 + 16 * s) * 2);
            mma16816(C1[0][2*jp+0], A1[0][s], b[0], b[1]);
            mma16816(C1[0][2*jp+1], A1[0][s], b[2], b[3]);
            mma16816(C1[1][2*jp+0], A1[1][s], b[0], b[1]);
            mma16816(C1[1][2*jp+1], A1[1][s], b[2], b[3]);
        }
    }

    int tq = L & 3, gq = L >> 2;
    float2 w2v[8];
    #pragma unroll
    for (int nt = 0; nt < 8; nt++) {
        w2v[nt].x = sW2[nt * 8 + 2 * tq + 0];
        w2v[nt].y = sW2[nt * 8 + 2 * tq + 1];
    }
    int base = blockIdx.x * 256 + w * 32;
    #pragma unroll
    for (int m = 0; m < 2; m++) {
        float p01 = 0.0f, p23 = 0.0f;
        #pragma unroll
        for (int nt = 0; nt < 8; nt++) {
            p01 = fmaf(fmaxf(C1[m][nt][0], 0.0f), w2v[nt].x, p01);
            p01 = fmaf(fmaxf(C1[m][nt][1], 0.0f), w2v[nt].y, p01);
            p23 = fmaf(fmaxf(C1[m][nt][2], 0.0f), w2v[nt].x, p23);
            p23 = fmaf(fmaxf(C1[m][nt][3], 0.0f), w2v[nt].y, p23);
        }
        p01 += __shfl_xor_sync(0xffffffffu, p01, 1);
        p01 += __shfl_xor_sync(0xffffffffu, p01, 2);
        p23 += __shfl_xor_sync(0xffffffffu, p23, 1);
        p23 += __shfl_xor_sync(0xffffffffu, p23, 2);
        if (tq == 0) {
            out[g_ridx[base + m * 16 + gq]]     = p01;
            out[g_ridx[base + m * 16 + 8 + gq]] = p23;
        }
    }
}

extern "C" void kernel_launch(void* const* d_in, const int* in_sizes, int n_in,
                              void* d_out, int out_size) {
    const float* x  = (const float*)d_in[0];
    const float* r  = (const float*)d_in[1];
    const float* s  = (const float*)d_in[2];
    const float* t  = (const float*)d_in[3];
    const float* f  = (const float*)d_in[4];
    const float* W0 = (const float*)d_in[5];
    const float* W1 = (const float*)d_in[6];
    const float* W2 = (const float*)d_in[7];
    float* out = (float*)d_out;

    cudaFuncSetAttribute(amgsrn_fused_kernel,
                         cudaFuncAttributeMaxDynamicSharedMemorySize, SMEM_TOTAL);

    prep_feat_hist_kernel<<<(NGRIDS * VOX + 255) / 256, 256>>>(f, x);   // 1
    scan_params_kernel<<<2, 1024>>>(r, s, t);                           // 2
    scatter_kernel<<<(NPTS + 255) / 256, 256>>>(x);                     // 3
    amgsrn_fused_kernel<<<NPTS / 256, 256, SMEM_TOTAL>>>(W0, W1, W2, out);  // 4 (ncu slot)
}